// round 2
// baseline (speedup 1.0000x reference)
#include <cuda_runtime.h>
#include <math.h>

#define H_IMG 1024
#define W_IMG 1280
#define NPIX  (H_IMG * W_IMG)
#define DAMPING 1e-6
#define DIST_THR_F 0.2f
#define NORM_THR_F 0.93969262078590838405f  /* cos(20 deg), rounds to correct fp32 */

// Persistent state across the kernel sequence (no device allocation allowed).
__device__ double g_poseD[16];   // current pose, fp64, row-major 4x4
__device__ float  g_poseF[12];   // [0..8] R row-major, [9..11] t (fp32 for reduce pass)
__device__ double g_accum[28];   // 21 JtJ (upper tri), 6 JtR, 1 valid count

// ---------------------------------------------------------------------------
__global__ void icp_init(const float* __restrict__ pose10) {
    if (threadIdx.x == 0 && blockIdx.x == 0) {
        #pragma unroll
        for (int i = 0; i < 16; i++) g_poseD[i] = (double)pose10[i];
        #pragma unroll
        for (int r = 0; r < 3; r++) {
            #pragma unroll
            for (int c = 0; c < 3; c++) g_poseF[r * 3 + c] = pose10[r * 4 + c];
            g_poseF[9 + r] = pose10[r * 4 + 3];
        }
        #pragma unroll
        for (int i = 0; i < 28; i++) g_accum[i] = 0.0;
    }
}

// ---------------------------------------------------------------------------
// Per-pixel residual/Jacobian + 28-way reduction into g_accum.
// All arithmetic feeding the round(u)/round(v) discretization uses IEEE
// round-to-nearest intrinsics so --use_fast_math cannot perturb the gather.
__global__ __launch_bounds__(256)
void icp_reduce(const float* __restrict__ v0d, const float* __restrict__ v1d,
                const float* __restrict__ n0d, const float* __restrict__ n1d,
                const float* __restrict__ Km)
{
    const float fx = Km[0], cx = Km[2], fy = Km[4], cy = Km[5];
    const float R00 = g_poseF[0], R01 = g_poseF[1], R02 = g_poseF[2];
    const float R10 = g_poseF[3], R11 = g_poseF[4], R12 = g_poseF[5];
    const float R20 = g_poseF[6], R21 = g_poseF[7], R22 = g_poseF[8];
    const float tx  = g_poseF[9], ty  = g_poseF[10], tz = g_poseF[11];

    float s[28];
    #pragma unroll
    for (int i = 0; i < 28; i++) s[i] = 0.f;

    const int stride = gridDim.x * blockDim.x;
    for (int idx = blockIdx.x * blockDim.x + threadIdx.x; idx < NPIX; idx += stride) {
        const float x  = v0d[3 * idx + 0];
        const float y  = v0d[3 * idx + 1];
        const float z  = v0d[3 * idx + 2];
        // deterministic fma chains (independent of fast-math contraction choices)
        const float px = __fmaf_rn(x, R00, __fmaf_rn(y, R01, __fmaf_rn(z, R02, tx)));
        const float py = __fmaf_rn(x, R10, __fmaf_rn(y, R11, __fmaf_rn(z, R12, ty)));
        const float pz = __fmaf_rn(x, R20, __fmaf_rn(y, R21, __fmaf_rn(z, R22, tz)));

        const float nx = n0d[3 * idx + 0];
        const float ny = n0d[3 * idx + 1];
        const float nz = n0d[3 * idx + 2];
        const float qx = __fmaf_rn(nx, R00, __fmaf_rn(ny, R01, __fmul_rn(nz, R02)));
        const float qy = __fmaf_rn(nx, R10, __fmaf_rn(ny, R11, __fmul_rn(nz, R12)));
        const float qz = __fmaf_rn(nx, R20, __fmaf_rn(ny, R21, __fmul_rn(nz, R22)));

        // IEEE-exact projection (immune to --use_fast_math approximate division)
        const float u = __fadd_rn(__fmul_rn(__fdiv_rn(px, pz), fx), cx);
        const float v = __fadd_rn(__fmul_rn(__fdiv_rn(py, pz), fy), cy);
        const bool inview = (u > 0.f) && (u < (float)(W_IMG - 1)) &&
                            (v > 0.f) && (v < (float)(H_IMG - 1));

        // nearest-neighbor gather (round-half-even matches jnp.round), clipped
        const float uif = fminf(fmaxf(rintf(u), 0.f), (float)(W_IMG - 1));
        const float vif = fminf(fmaxf(rintf(v), 0.f), (float)(H_IMG - 1));
        const int g = (int)vif * W_IMG + (int)uif;

        const float ax = v1d[3 * g + 0];
        const float ay = v1d[3 * g + 1];
        const float az = v1d[3 * g + 2];
        const float bx = n1d[3 * g + 0];
        const float by = n1d[3 * g + 1];
        const float bz = n1d[3 * g + 2];

        const float dx = __fadd_rn(px, -ax);
        const float dy = __fadd_rn(py, -ay);
        const float dz = __fadd_rn(pz, -az);
        // mirror reference: norm(diff) > 0.2  (exact sqrt, exact compare)
        const float dist = __fsqrt_rn(__fmaf_rn(dx, dx, __fmaf_rn(dy, dy, __fmul_rn(dz, dz))));
        const float ndot = __fmaf_rn(qx, bx, __fmaf_rn(qy, by, __fmul_rn(qz, bz)));

        const bool valid = inview && !(dist > DIST_THR_F) &&
                           (z > 0.f) && (az > 0.f) &&
                           (ndot > NORM_THR_F);
        if (valid) {
            const float r = __fmaf_rn(bx, dx, __fmaf_rn(by, dy, __fmul_rn(bz, dz)));
            float J[6];
            J[0] = __fadd_rn(__fmul_rn(py, bz), -__fmul_rn(pz, by));
            J[1] = __fadd_rn(__fmul_rn(pz, bx), -__fmul_rn(px, bz));
            J[2] = __fadd_rn(__fmul_rn(px, by), -__fmul_rn(py, bx));
            J[3] = bx; J[4] = by; J[5] = bz;
            int k = 0;
            #pragma unroll
            for (int i = 0; i < 6; i++)
                #pragma unroll
                for (int j = i; j < 6; j++) s[k++] = __fmaf_rn(J[i], J[j], s[k]);
            #pragma unroll
            for (int i = 0; i < 6; i++) s[21 + i] = __fmaf_rn(J[i], r, s[21 + i]);
            s[27] += 1.f;
        }
    }

    // warp reduction (fp32 — each thread only summed ~4-5 px)
    #pragma unroll
    for (int i = 0; i < 28; i++) {
        #pragma unroll
        for (int o = 16; o > 0; o >>= 1)
            s[i] += __shfl_down_sync(0xffffffffu, s[i], o);
    }

    __shared__ double sh[28];
    if (threadIdx.x < 28) sh[threadIdx.x] = 0.0;
    __syncthreads();
    if ((threadIdx.x & 31) == 0) {
        #pragma unroll
        for (int i = 0; i < 28; i++) atomicAdd(&sh[i], (double)s[i]);
    }
    __syncthreads();
    if (threadIdx.x < 28) atomicAdd(&g_accum[threadIdx.x], sh[threadIdx.x]);
}

// ---------------------------------------------------------------------------
// Single-thread fp64: damped 6x6 solve, se3 exp, pose update, accum reset.
__global__ void icp_solve(int write_out, float* __restrict__ out, int out_size)
{
    if (threadIdx.x != 0 || blockIdx.x != 0) return;

    double M[6][7];
    {
        int k = 0;
        double A[6][6];
        for (int i = 0; i < 6; i++)
            for (int j = i; j < 6; j++) { A[i][j] = g_accum[k]; A[j][i] = g_accum[k]; k++; }
        double tr = 0.0;
        for (int i = 0; i < 6; i++) tr += A[i][i];
        for (int i = 0; i < 6; i++) A[i][i] += tr * DAMPING;
        for (int i = 0; i < 6; i++) {
            for (int j = 0; j < 6; j++) M[i][j] = A[i][j];
            M[i][6] = g_accum[21 + i];
        }
    }
    const double count = g_accum[27];

    // Gauss-Jordan with partial pivoting
    for (int c = 0; c < 6; c++) {
        int piv = c; double best = fabs(M[c][c]);
        for (int r2 = c + 1; r2 < 6; r2++) {
            double a = fabs(M[r2][c]);
            if (a > best) { best = a; piv = r2; }
        }
        if (piv != c)
            for (int j = 0; j < 7; j++) { double t = M[c][j]; M[c][j] = M[piv][j]; M[piv][j] = t; }
        const double inv = 1.0 / M[c][c];
        for (int r2 = 0; r2 < 6; r2++) {
            if (r2 == c) continue;
            const double f = M[r2][c] * inv;
            for (int j = c; j < 7; j++) M[r2][j] -= f * M[c][j];
        }
    }
    double xi[6];
    for (int i = 0; i < 6; i++) xi[i] = -M[i][6] / M[i][i];

    // exp_se3(xi)
    const double w0 = xi[0], w1 = xi[1], w2 = xi[2];
    const double vx = xi[3], vy = xi[4], vz = xi[5];
    const double theta = sqrt(w0 * w0 + w1 * w1 + w2 * w2);
    double E[3][3], Jm[3][3];
    if (theta <= 1e-8) {
        for (int i = 0; i < 3; i++)
            for (int j = 0; j < 3; j++) {
                E[i][j]  = (i == j) ? 1.0 : 0.0;
                Jm[i][j] = (i == j) ? 1.0 : 0.0;
            }
    } else {
        const double wh[3][3]  = { {0.0, -w2,  w1}, { w2, 0.0, -w0}, {-w1,  w0, 0.0} };
        double wh2[3][3];
        for (int i = 0; i < 3; i++)
            for (int j = 0; j < 3; j++) {
                double acc = 0.0;
                for (int k = 0; k < 3; k++) acc += wh[i][k] * wh[k][j];
                wh2[i][j] = acc;
            }
        const double st = sin(theta), ct = cos(theta);
        const double a = st / theta;
        const double b = (1.0 - ct) / (theta * theta);
        const double c = (theta - st) / (theta * theta * theta);
        for (int i = 0; i < 3; i++)
            for (int j = 0; j < 3; j++) {
                const double eye = (i == j) ? 1.0 : 0.0;
                E[i][j]  = eye + a * wh[i][j] + b * wh2[i][j];
                Jm[i][j] = eye + b * wh[i][j] + c * wh2[i][j];
            }
    }
    double T[16];
    for (int i = 0; i < 3; i++) {
        for (int j = 0; j < 3; j++) T[i * 4 + j] = E[i][j];
        T[i * 4 + 3] = Jm[i][0] * vx + Jm[i][1] * vy + Jm[i][2] * vz;
    }
    T[12] = 0.0; T[13] = 0.0; T[14] = 0.0; T[15] = 1.0;

    // pose = T @ pose
    double P[16];
    for (int i = 0; i < 4; i++)
        for (int j = 0; j < 4; j++) {
            double acc = 0.0;
            for (int k = 0; k < 4; k++) acc += T[i * 4 + k] * g_poseD[k * 4 + j];
            P[i * 4 + j] = acc;
        }
    for (int i = 0; i < 16; i++) g_poseD[i] = P[i];
    for (int r = 0; r < 3; r++) {
        for (int c = 0; c < 3; c++) g_poseF[r * 3 + c] = (float)P[r * 4 + c];
        g_poseF[9 + r] = (float)P[r * 4 + 3];
    }

    if (write_out) {
        for (int i = 0; i < 16 && i < out_size; i++) out[i] = (float)P[i];
        if (out_size >= 17) out[16] = (float)(count / (double)NPIX);
    }
    for (int i = 0; i < 28; i++) g_accum[i] = 0.0;
}

// ---------------------------------------------------------------------------
extern "C" void kernel_launch(void* const* d_in, const int* in_sizes, int n_in,
                              void* d_out, int out_size)
{
    const float* pose10 = (const float*)d_in[0];  // 16
    const float* v0     = (const float*)d_in[1];  // H*W*3
    const float* v1     = (const float*)d_in[2];  // H*W*3
    const float* n0     = (const float*)d_in[3];  // H*W*3
    const float* n1     = (const float*)d_in[4];  // H*W*3
    const float* K      = (const float*)d_in[5];  // 9
    float* out = (float*)d_out;

    icp_init<<<1, 32>>>(pose10);
    for (int it = 0; it < 3; ++it) {
        icp_reduce<<<1184, 256>>>(v0, v1, n0, n1, K);
        icp_solve<<<1, 1>>>(it == 2 ? 1 : 0, out, out_size);
    }
}

// round 3
// speedup vs baseline: 1.1120x; 1.1120x over previous
#include <cuda_runtime.h>
#include <math.h>

#define H_IMG 1024
#define W_IMG 1280
#define NPIX  (H_IMG * W_IMG)
#define DAMPING 1e-6
#define DIST_THR_F 0.2f
#define NORM_THR_F 0.93969262078590838405f  /* cos(20 deg) */

#define RED_BLOCKS 1280
#define RED_THREADS 256
// 1280*256 threads * 4 px = 1310720 = NPIX exactly

// Persistent state (no device allocation allowed).
__device__ double g_poseD[16];        // current pose, fp64, row-major 4x4
__device__ float  g_poseF[12];        // [0..8] R row-major, [9..11] t
__device__ double g_accum[28];        // 21 JtJ upper-tri, 6 JtR, 1 count
__device__ unsigned int g_done;      // last-block-done counter

// ---------------------------------------------------------------------------
__global__ void icp_init(const float* __restrict__ pose10) {
    if (threadIdx.x == 0 && blockIdx.x == 0) {
        #pragma unroll
        for (int i = 0; i < 16; i++) g_poseD[i] = (double)pose10[i];
        #pragma unroll
        for (int r = 0; r < 3; r++) {
            #pragma unroll
            for (int c = 0; c < 3; c++) g_poseF[r * 3 + c] = pose10[r * 4 + c];
            g_poseF[9 + r] = pose10[r * 4 + 3];
        }
        #pragma unroll
        for (int i = 0; i < 28; i++) g_accum[i] = 0.0;
        g_done = 0;
    }
}

// ---------------------------------------------------------------------------
// fp64 solve, runs on one thread (device function, called by last block).
__device__ void solve_update(int write_out, float* out, int out_size)
{
    double M[6][7];
    {
        int k = 0;
        double A[6][6];
        for (int i = 0; i < 6; i++)
            for (int j = i; j < 6; j++) { A[i][j] = g_accum[k]; A[j][i] = g_accum[k]; k++; }
        double tr = 0.0;
        for (int i = 0; i < 6; i++) tr += A[i][i];
        for (int i = 0; i < 6; i++) A[i][i] += tr * DAMPING;
        for (int i = 0; i < 6; i++) {
            for (int j = 0; j < 6; j++) M[i][j] = A[i][j];
            M[i][6] = g_accum[21 + i];
        }
    }
    const double count = g_accum[27];

    // Gauss-Jordan with partial pivoting
    for (int c = 0; c < 6; c++) {
        int piv = c; double best = fabs(M[c][c]);
        for (int r2 = c + 1; r2 < 6; r2++) {
            double a = fabs(M[r2][c]);
            if (a > best) { best = a; piv = r2; }
        }
        if (piv != c)
            for (int j = 0; j < 7; j++) { double t = M[c][j]; M[c][j] = M[piv][j]; M[piv][j] = t; }
        const double inv = 1.0 / M[c][c];
        for (int r2 = 0; r2 < 6; r2++) {
            if (r2 == c) continue;
            const double f = M[r2][c] * inv;
            for (int j = c; j < 7; j++) M[r2][j] -= f * M[c][j];
        }
    }
    double xi[6];
    for (int i = 0; i < 6; i++) xi[i] = -M[i][6] / M[i][i];

    // exp_se3(xi)
    const double w0 = xi[0], w1 = xi[1], w2 = xi[2];
    const double vx = xi[3], vy = xi[4], vz = xi[5];
    const double theta = sqrt(w0 * w0 + w1 * w1 + w2 * w2);
    double E[3][3], Jm[3][3];
    if (theta <= 1e-8) {
        for (int i = 0; i < 3; i++)
            for (int j = 0; j < 3; j++) {
                E[i][j]  = (i == j) ? 1.0 : 0.0;
                Jm[i][j] = (i == j) ? 1.0 : 0.0;
            }
    } else {
        const double wh[3][3]  = { {0.0, -w2,  w1}, { w2, 0.0, -w0}, {-w1,  w0, 0.0} };
        double wh2[3][3];
        for (int i = 0; i < 3; i++)
            for (int j = 0; j < 3; j++) {
                double acc = 0.0;
                for (int k = 0; k < 3; k++) acc += wh[i][k] * wh[k][j];
                wh2[i][j] = acc;
            }
        const double st = sin(theta), ct = cos(theta);
        const double a = st / theta;
        const double b = (1.0 - ct) / (theta * theta);
        const double c = (theta - st) / (theta * theta * theta);
        for (int i = 0; i < 3; i++)
            for (int j = 0; j < 3; j++) {
                const double eye = (i == j) ? 1.0 : 0.0;
                E[i][j]  = eye + a * wh[i][j] + b * wh2[i][j];
                Jm[i][j] = eye + b * wh[i][j] + c * wh2[i][j];
            }
    }
    double T[16];
    for (int i = 0; i < 3; i++) {
        for (int j = 0; j < 3; j++) T[i * 4 + j] = E[i][j];
        T[i * 4 + 3] = Jm[i][0] * vx + Jm[i][1] * vy + Jm[i][2] * vz;
    }
    T[12] = 0.0; T[13] = 0.0; T[14] = 0.0; T[15] = 1.0;

    double P[16];
    for (int i = 0; i < 4; i++)
        for (int j = 0; j < 4; j++) {
            double acc = 0.0;
            for (int k = 0; k < 4; k++) acc += T[i * 4 + k] * g_poseD[k * 4 + j];
            P[i * 4 + j] = acc;
        }
    for (int i = 0; i < 16; i++) g_poseD[i] = P[i];
    for (int r = 0; r < 3; r++) {
        for (int c = 0; c < 3; c++) g_poseF[r * 3 + c] = (float)P[r * 4 + c];
        g_poseF[9 + r] = (float)P[r * 4 + 3];
    }

    if (write_out) {
        for (int i = 0; i < 16 && i < out_size; i++) out[i] = (float)P[i];
        if (out_size >= 17) out[16] = (float)(count / (double)NPIX);
    }
    for (int i = 0; i < 28; i++) g_accum[i] = 0.0;
    __threadfence();
    g_done = 0;   // reset for next launch (serialized by kernel boundary)
}

// ---------------------------------------------------------------------------
// Per-pixel body: branchless accumulate (J,r zeroed when invalid, matching
// reference's where()). Exact-rounding intrinsics keep the round(u/v)
// discretization identical under --use_fast_math.
__device__ __forceinline__ void px_body(
    float x, float y, float z, float nx, float ny, float nz,
    const float* __restrict__ v1d, const float* __restrict__ n1d,
    float fx, float fy, float cx, float cy,
    float R00, float R01, float R02, float R10, float R11, float R12,
    float R20, float R21, float R22, float tx, float ty, float tz,
    float* s)
{
    const float px = __fmaf_rn(x, R00, __fmaf_rn(y, R01, __fmaf_rn(z, R02, tx)));
    const float py = __fmaf_rn(x, R10, __fmaf_rn(y, R11, __fmaf_rn(z, R12, ty)));
    const float pz = __fmaf_rn(x, R20, __fmaf_rn(y, R21, __fmaf_rn(z, R22, tz)));

    const float qx = __fmaf_rn(nx, R00, __fmaf_rn(ny, R01, __fmul_rn(nz, R02)));
    const float qy = __fmaf_rn(nx, R10, __fmaf_rn(ny, R11, __fmul_rn(nz, R12)));
    const float qz = __fmaf_rn(nx, R20, __fmaf_rn(ny, R21, __fmul_rn(nz, R22)));

    const float u = __fadd_rn(__fmul_rn(__fdiv_rn(px, pz), fx), cx);
    const float v = __fadd_rn(__fmul_rn(__fdiv_rn(py, pz), fy), cy);
    const bool inview = (u > 0.f) && (u < (float)(W_IMG - 1)) &&
                        (v > 0.f) && (v < (float)(H_IMG - 1));

    const float uif = fminf(fmaxf(rintf(u), 0.f), (float)(W_IMG - 1));
    const float vif = fminf(fmaxf(rintf(v), 0.f), (float)(H_IMG - 1));
    const int g = (int)vif * W_IMG + (int)uif;

    const float ax = v1d[3 * g + 0];
    const float ay = v1d[3 * g + 1];
    const float az = v1d[3 * g + 2];
    const float bx = n1d[3 * g + 0];
    const float by = n1d[3 * g + 1];
    const float bz = n1d[3 * g + 2];

    const float dx = __fadd_rn(px, -ax);
    const float dy = __fadd_rn(py, -ay);
    const float dz = __fadd_rn(pz, -az);
    const float dist = __fsqrt_rn(__fmaf_rn(dx, dx, __fmaf_rn(dy, dy, __fmul_rn(dz, dz))));
    const float ndot = __fmaf_rn(qx, bx, __fmaf_rn(qy, by, __fmul_rn(qz, bz)));

    const bool valid = inview && !(dist > DIST_THR_F) &&
                       (z > 0.f) && (az > 0.f) && (ndot > NORM_THR_F);

    float r = __fmaf_rn(bx, dx, __fmaf_rn(by, dy, __fmul_rn(bz, dz)));
    float J[6];
    J[0] = __fadd_rn(__fmul_rn(py, bz), -__fmul_rn(pz, by));
    J[1] = __fadd_rn(__fmul_rn(pz, bx), -__fmul_rn(px, bz));
    J[2] = __fadd_rn(__fmul_rn(px, by), -__fmul_rn(py, bx));
    J[3] = bx; J[4] = by; J[5] = bz;
    if (!valid) {
        r = 0.f;
        #pragma unroll
        for (int i = 0; i < 6; i++) J[i] = 0.f;
    }
    int k = 0;
    #pragma unroll
    for (int i = 0; i < 6; i++)
        #pragma unroll
        for (int j = i; j < 6; j++) { s[k] = __fmaf_rn(J[i], J[j], s[k]); k++; }
    #pragma unroll
    for (int i = 0; i < 6; i++) s[21 + i] = __fmaf_rn(J[i], r, s[21 + i]);
    if (valid) s[27] += 1.f;
}

// ---------------------------------------------------------------------------
__global__ __launch_bounds__(RED_THREADS)
void icp_reduce(const float* __restrict__ v0d, const float* __restrict__ v1d,
                const float* __restrict__ n0d, const float* __restrict__ n1d,
                const float* __restrict__ Km,
                int write_out, float* __restrict__ out, int out_size)
{
    const float fx = Km[0], cx = Km[2], fy = Km[4], cy = Km[5];
    const float R00 = g_poseF[0], R01 = g_poseF[1], R02 = g_poseF[2];
    const float R10 = g_poseF[3], R11 = g_poseF[4], R12 = g_poseF[5];
    const float R20 = g_poseF[6], R21 = g_poseF[7], R22 = g_poseF[8];
    const float tx  = g_poseF[9], ty  = g_poseF[10], tz = g_poseF[11];

    float s[28];
    #pragma unroll
    for (int i = 0; i < 28; i++) s[i] = 0.f;

    // Each thread owns exactly 4 consecutive pixels: vectorized 16B loads.
    const int t = blockIdx.x * RED_THREADS + threadIdx.x;   // group index
    const float4* v0q = (const float4*)(v0d) + 3 * t;       // 48B per group
    const float4* n0q = (const float4*)(n0d) + 3 * t;
    const float4 a0 = v0q[0], a1 = v0q[1], a2 = v0q[2];
    const float4 b0 = n0q[0], b1 = n0q[1], b2 = n0q[2];

    px_body(a0.x, a0.y, a0.z, b0.x, b0.y, b0.z, v1d, n1d, fx, fy, cx, cy,
            R00, R01, R02, R10, R11, R12, R20, R21, R22, tx, ty, tz, s);
    px_body(a0.w, a1.x, a1.y, b0.w, b1.x, b1.y, v1d, n1d, fx, fy, cx, cy,
            R00, R01, R02, R10, R11, R12, R20, R21, R22, tx, ty, tz, s);
    px_body(a1.z, a1.w, a2.x, b1.z, b1.w, b2.x, v1d, n1d, fx, fy, cx, cy,
            R00, R01, R02, R10, R11, R12, R20, R21, R22, tx, ty, tz, s);
    px_body(a2.y, a2.z, a2.w, b2.y, b2.z, b2.w, v1d, n1d, fx, fy, cx, cy,
            R00, R01, R02, R10, R11, R12, R20, R21, R22, tx, ty, tz, s);

    // warp reduction
    #pragma unroll
    for (int i = 0; i < 28; i++) {
        #pragma unroll
        for (int o = 16; o > 0; o >>= 1)
            s[i] += __shfl_down_sync(0xffffffffu, s[i], o);
    }

    __shared__ double sh[28];
    if (threadIdx.x < 28) sh[threadIdx.x] = 0.0;
    __syncthreads();
    if ((threadIdx.x & 31) == 0) {
        #pragma unroll
        for (int i = 0; i < 28; i++) atomicAdd(&sh[i], (double)s[i]);
    }
    __syncthreads();
    if (threadIdx.x < 28) atomicAdd(&g_accum[threadIdx.x], sh[threadIdx.x]);

    // Last-block-done: the final block runs the fp64 solve inline.
    __shared__ unsigned int s_last;
    if (threadIdx.x == 0) {
        __threadfence();
        s_last = atomicAdd(&g_done, 1u);
    }
    __syncthreads();
    if (s_last == gridDim.x - 1 && threadIdx.x == 0) {
        solve_update(write_out, out, out_size);
    }
}

// ---------------------------------------------------------------------------
extern "C" void kernel_launch(void* const* d_in, const int* in_sizes, int n_in,
                              void* d_out, int out_size)
{
    const float* pose10 = (const float*)d_in[0];  // 16
    const float* v0     = (const float*)d_in[1];  // H*W*3
    const float* v1     = (const float*)d_in[2];  // H*W*3
    const float* n0     = (const float*)d_in[3];  // H*W*3
    const float* n1     = (const float*)d_in[4];  // H*W*3
    const float* K      = (const float*)d_in[5];  // 9
    float* out = (float*)d_out;

    icp_init<<<1, 32>>>(pose10);
    for (int it = 0; it < 3; ++it) {
        icp_reduce<<<RED_BLOCKS, RED_THREADS>>>(v0, v1, n0, n1, K,
                                                it == 2 ? 1 : 0, out, out_size);
    }
}

// round 4
// speedup vs baseline: 1.1797x; 1.0609x over previous
#include <cuda_runtime.h>
#include <math.h>

#define H_IMG 1024
#define W_IMG 1280
#define NPIX  (H_IMG * W_IMG)
#define DAMPING 1e-6
#define DIST_THR_F 0.2f
#define NORM_THR_F 0.93969262078590838405f  /* cos(20 deg) */

#define RED_BLOCKS 640
#define RED_THREADS 256
// 640 * 256 threads * 8 px = 1310720 = NPIX exactly

// Persistent state (no device allocation allowed).
__device__ double g_poseD[16];        // current pose, fp64, row-major 4x4
__device__ float  g_poseF[12];        // [0..8] R row-major, [9..11] t
__device__ double g_accum[28];        // 21 JtJ upper-tri, 6 JtR, 1 count
__device__ unsigned int g_done;       // last-block-done counter

// ---------------------------------------------------------------------------
__global__ void icp_init(const float* __restrict__ pose10) {
    if (threadIdx.x == 0 && blockIdx.x == 0) {
        #pragma unroll
        for (int i = 0; i < 16; i++) g_poseD[i] = (double)pose10[i];
        #pragma unroll
        for (int r = 0; r < 3; r++) {
            #pragma unroll
            for (int c = 0; c < 3; c++) g_poseF[r * 3 + c] = pose10[r * 4 + c];
            g_poseF[9 + r] = pose10[r * 4 + 3];
        }
        #pragma unroll
        for (int i = 0; i < 28; i++) g_accum[i] = 0.0;
        g_done = 0;
    }
}

// ---------------------------------------------------------------------------
// fp64 solve on one thread: LDLT 6x6, se3 exp via Taylor-in-theta^2 (no
// double sin/cos/sqrt on the hot path), pose update, state reset.
__device__ void solve_update(int write_out, float* out, int out_size)
{
    double A[6][6], b[6];
    {
        int k = 0;
        for (int i = 0; i < 6; i++)
            for (int j = i; j < 6; j++) { A[i][j] = g_accum[k]; A[j][i] = g_accum[k]; k++; }
        double tr = 0.0;
        for (int i = 0; i < 6; i++) tr += A[i][i];
        for (int i = 0; i < 6; i++) A[i][i] += tr * DAMPING;
        for (int i = 0; i < 6; i++) b[i] = g_accum[21 + i];
    }
    const double count = g_accum[27];

    // LDLT factorization (SPD by construction + damping)
    double L[6][6], D[6];
    for (int j = 0; j < 6; j++) {
        double dj = A[j][j];
        for (int k = 0; k < j; k++) dj -= L[j][k] * L[j][k] * D[k];
        D[j] = dj;
        L[j][j] = 1.0;
        for (int i = j + 1; i < 6; i++) {
            double v = A[i][j];
            for (int k = 0; k < j; k++) v -= L[i][k] * L[j][k] * D[k];
            L[i][j] = v / dj;
        }
    }
    // Solve L y = b ; D z = y ; L^T x = z ; xi = -x
    double y[6];
    for (int i = 0; i < 6; i++) {
        double v = b[i];
        for (int k = 0; k < i; k++) v -= L[i][k] * y[k];
        y[i] = v;
    }
    double xi[6];
    for (int i = 5; i >= 0; i--) {
        double v = y[i] / D[i];
        for (int k = i + 1; k < 6; k++) v -= L[k][i] * xi[k];
        xi[i] = v;
    }
    for (int i = 0; i < 6; i++) xi[i] = -xi[i];

    // exp_se3(xi): A=sin(t)/t, B=(1-cos t)/t^2, C=(t-sin t)/t^3 — even in t,
    // evaluate as series in t2 (exact to ~1e-15 for t2 < 0.25).
    const double w0 = xi[0], w1 = xi[1], w2 = xi[2];
    const double vx = xi[3], vy = xi[4], vz = xi[5];
    const double t2 = w0 * w0 + w1 * w1 + w2 * w2;
    double E[3][3], Jm[3][3];
    if (t2 <= 1e-16) {
        for (int i = 0; i < 3; i++)
            for (int j = 0; j < 3; j++) {
                E[i][j]  = (i == j) ? 1.0 : 0.0;
                Jm[i][j] = (i == j) ? 1.0 : 0.0;
            }
    } else {
        double cA, cB, cC;
        if (t2 < 0.25) {
            cA = 1.0 + t2 * (-1.0 / 6.0 + t2 * (1.0 / 120.0 + t2 * (-1.0 / 5040.0 +
                 t2 * (1.0 / 362880.0 + t2 * (-1.0 / 39916800.0)))));
            cB = 0.5 + t2 * (-1.0 / 24.0 + t2 * (1.0 / 720.0 + t2 * (-1.0 / 40320.0 +
                 t2 * (1.0 / 3628800.0 + t2 * (-1.0 / 479001600.0)))));
            cC = 1.0 / 6.0 + t2 * (-1.0 / 120.0 + t2 * (1.0 / 5040.0 + t2 * (-1.0 / 362880.0 +
                 t2 * (1.0 / 39916800.0 + t2 * (-1.0 / 6227020800.0)))));
        } else {
            const double th = sqrt(t2);
            const double st = sin(th), ct = cos(th);
            cA = st / th;
            cB = (1.0 - ct) / t2;
            cC = (th - st) / (t2 * th);
        }
        const double wh[3][3] = { {0.0, -w2,  w1}, { w2, 0.0, -w0}, {-w1,  w0, 0.0} };
        double wh2[3][3];
        for (int i = 0; i < 3; i++)
            for (int j = 0; j < 3; j++) {
                double acc = 0.0;
                for (int k = 0; k < 3; k++) acc += wh[i][k] * wh[k][j];
                wh2[i][j] = acc;
            }
        for (int i = 0; i < 3; i++)
            for (int j = 0; j < 3; j++) {
                const double eye = (i == j) ? 1.0 : 0.0;
                E[i][j]  = eye + cA * wh[i][j] + cB * wh2[i][j];
                Jm[i][j] = eye + cB * wh[i][j] + cC * wh2[i][j];
            }
    }
    double T[16];
    for (int i = 0; i < 3; i++) {
        for (int j = 0; j < 3; j++) T[i * 4 + j] = E[i][j];
        T[i * 4 + 3] = Jm[i][0] * vx + Jm[i][1] * vy + Jm[i][2] * vz;
    }
    T[12] = 0.0; T[13] = 0.0; T[14] = 0.0; T[15] = 1.0;

    double P[16];
    for (int i = 0; i < 4; i++)
        for (int j = 0; j < 4; j++) {
            double acc = 0.0;
            for (int k = 0; k < 4; k++) acc += T[i * 4 + k] * g_poseD[k * 4 + j];
            P[i * 4 + j] = acc;
        }
    for (int i = 0; i < 16; i++) g_poseD[i] = P[i];
    for (int r = 0; r < 3; r++) {
        for (int c = 0; c < 3; c++) g_poseF[r * 3 + c] = (float)P[r * 4 + c];
        g_poseF[9 + r] = (float)P[r * 4 + 3];
    }

    if (write_out) {
        for (int i = 0; i < 16 && i < out_size; i++) out[i] = (float)P[i];
        if (out_size >= 17) out[16] = (float)(count / (double)NPIX);
    }
    for (int i = 0; i < 28; i++) g_accum[i] = 0.0;
    __threadfence();
    g_done = 0;   // reset for next launch (serialized by kernel boundary)
}

// ---------------------------------------------------------------------------
// Per-pixel body: branchless accumulate; exact-rounding intrinsics keep the
// round(u/v) discretization identical under --use_fast_math.
__device__ __forceinline__ void px_body(
    float x, float y, float z, float nx, float ny, float nz,
    const float* __restrict__ v1d, const float* __restrict__ n1d,
    float fx, float fy, float cx, float cy,
    float R00, float R01, float R02, float R10, float R11, float R12,
    float R20, float R21, float R22, float tx, float ty, float tz,
    float* s)
{
    const float px = __fmaf_rn(x, R00, __fmaf_rn(y, R01, __fmaf_rn(z, R02, tx)));
    const float py = __fmaf_rn(x, R10, __fmaf_rn(y, R11, __fmaf_rn(z, R12, ty)));
    const float pz = __fmaf_rn(x, R20, __fmaf_rn(y, R21, __fmaf_rn(z, R22, tz)));

    const float qx = __fmaf_rn(nx, R00, __fmaf_rn(ny, R01, __fmul_rn(nz, R02)));
    const float qy = __fmaf_rn(nx, R10, __fmaf_rn(ny, R11, __fmul_rn(nz, R12)));
    const float qz = __fmaf_rn(nx, R20, __fmaf_rn(ny, R21, __fmul_rn(nz, R22)));

    const float u = __fadd_rn(__fmul_rn(__fdiv_rn(px, pz), fx), cx);
    const float v = __fadd_rn(__fmul_rn(__fdiv_rn(py, pz), fy), cy);
    const bool inview = (u > 0.f) && (u < (float)(W_IMG - 1)) &&
                        (v > 0.f) && (v < (float)(H_IMG - 1));

    const float uif = fminf(fmaxf(rintf(u), 0.f), (float)(W_IMG - 1));
    const float vif = fminf(fmaxf(rintf(v), 0.f), (float)(H_IMG - 1));
    const int g = (int)vif * W_IMG + (int)uif;

    const float ax = v1d[3 * g + 0];
    const float ay = v1d[3 * g + 1];
    const float az = v1d[3 * g + 2];
    const float bx = n1d[3 * g + 0];
    const float by = n1d[3 * g + 1];
    const float bz = n1d[3 * g + 2];

    const float dx = __fadd_rn(px, -ax);
    const float dy = __fadd_rn(py, -ay);
    const float dz = __fadd_rn(pz, -az);
    const float dist = __fsqrt_rn(__fmaf_rn(dx, dx, __fmaf_rn(dy, dy, __fmul_rn(dz, dz))));
    const float ndot = __fmaf_rn(qx, bx, __fmaf_rn(qy, by, __fmul_rn(qz, bz)));

    const bool valid = inview && !(dist > DIST_THR_F) &&
                       (z > 0.f) && (az > 0.f) && (ndot > NORM_THR_F);

    float r = __fmaf_rn(bx, dx, __fmaf_rn(by, dy, __fmul_rn(bz, dz)));
    float J[6];
    J[0] = __fadd_rn(__fmul_rn(py, bz), -__fmul_rn(pz, by));
    J[1] = __fadd_rn(__fmul_rn(pz, bx), -__fmul_rn(px, bz));
    J[2] = __fadd_rn(__fmul_rn(px, by), -__fmul_rn(py, bx));
    J[3] = bx; J[4] = by; J[5] = bz;
    if (!valid) {
        r = 0.f;
        #pragma unroll
        for (int i = 0; i < 6; i++) J[i] = 0.f;
    }
    int k = 0;
    #pragma unroll
    for (int i = 0; i < 6; i++)
        #pragma unroll
        for (int j = i; j < 6; j++) { s[k] = __fmaf_rn(J[i], J[j], s[k]); k++; }
    #pragma unroll
    for (int i = 0; i < 6; i++) s[21 + i] = __fmaf_rn(J[i], r, s[21 + i]);
    if (valid) s[27] += 1.f;
}

// ---------------------------------------------------------------------------
__global__ __launch_bounds__(RED_THREADS, 2)
void icp_reduce(const float* __restrict__ v0d, const float* __restrict__ v1d,
                const float* __restrict__ n0d, const float* __restrict__ n1d,
                const float* __restrict__ Km,
                int write_out, float* __restrict__ out, int out_size)
{
    const float fx = Km[0], cx = Km[2], fy = Km[4], cy = Km[5];
    const float R00 = g_poseF[0], R01 = g_poseF[1], R02 = g_poseF[2];
    const float R10 = g_poseF[3], R11 = g_poseF[4], R12 = g_poseF[5];
    const float R20 = g_poseF[6], R21 = g_poseF[7], R22 = g_poseF[8];
    const float tx  = g_poseF[9], ty  = g_poseF[10], tz = g_poseF[11];

    float s[28];
    #pragma unroll
    for (int i = 0; i < 28; i++) s[i] = 0.f;

    // Each thread owns exactly 8 consecutive pixels = 6 float4 per array.
    const int t = blockIdx.x * RED_THREADS + threadIdx.x;   // group index
    const float4* v0q = (const float4*)(v0d) + 6 * t;       // 96B per group
    const float4* n0q = (const float4*)(n0d) + 6 * t;

    #pragma unroll
    for (int h = 0; h < 2; h++) {                            // 2 half-groups of 4 px
        const float4 a0 = v0q[3 * h + 0], a1 = v0q[3 * h + 1], a2 = v0q[3 * h + 2];
        const float4 b0 = n0q[3 * h + 0], b1 = n0q[3 * h + 1], b2 = n0q[3 * h + 2];
        px_body(a0.x, a0.y, a0.z, b0.x, b0.y, b0.z, v1d, n1d, fx, fy, cx, cy,
                R00, R01, R02, R10, R11, R12, R20, R21, R22, tx, ty, tz, s);
        px_body(a0.w, a1.x, a1.y, b0.w, b1.x, b1.y, v1d, n1d, fx, fy, cx, cy,
                R00, R01, R02, R10, R11, R12, R20, R21, R22, tx, ty, tz, s);
        px_body(a1.z, a1.w, a2.x, b1.z, b1.w, b2.x, v1d, n1d, fx, fy, cx, cy,
                R00, R01, R02, R10, R11, R12, R20, R21, R22, tx, ty, tz, s);
        px_body(a2.y, a2.z, a2.w, b2.y, b2.z, b2.w, v1d, n1d, fx, fy, cx, cy,
                R00, R01, R02, R10, R11, R12, R20, R21, R22, tx, ty, tz, s);
    }

    // warp reduction
    #pragma unroll
    for (int i = 0; i < 28; i++) {
        #pragma unroll
        for (int o = 16; o > 0; o >>= 1)
            s[i] += __shfl_down_sync(0xffffffffu, s[i], o);
    }

    __shared__ double sh[28];
    if (threadIdx.x < 28) sh[threadIdx.x] = 0.0;
    __syncthreads();
    if ((threadIdx.x & 31) == 0) {
        #pragma unroll
        for (int i = 0; i < 28; i++) atomicAdd(&sh[i], (double)s[i]);
    }
    __syncthreads();
    if (threadIdx.x < 28) atomicAdd(&g_accum[threadIdx.x], sh[threadIdx.x]);

    // Last-block-done: the final block runs the fp64 solve inline.
    __shared__ unsigned int s_last;
    if (threadIdx.x == 0) {
        __threadfence();
        s_last = atomicAdd(&g_done, 1u);
    }
    __syncthreads();
    if (s_last == gridDim.x - 1 && threadIdx.x == 0) {
        solve_update(write_out, out, out_size);
    }
}

// ---------------------------------------------------------------------------
extern "C" void kernel_launch(void* const* d_in, const int* in_sizes, int n_in,
                              void* d_out, int out_size)
{
    const float* pose10 = (const float*)d_in[0];  // 16
    const float* v0     = (const float*)d_in[1];  // H*W*3
    const float* v1     = (const float*)d_in[2];  // H*W*3
    const float* n0     = (const float*)d_in[3];  // H*W*3
    const float* n1     = (const float*)d_in[4];  // H*W*3
    const float* K      = (const float*)d_in[5];  // 9
    float* out = (float*)d_out;

    icp_init<<<1, 32>>>(pose10);
    for (int it = 0; it < 3; ++it) {
        icp_reduce<<<RED_BLOCKS, RED_THREADS>>>(v0, v1, n0, n1, K,
                                                it == 2 ? 1 : 0, out, out_size);
    }
}

// round 5
// speedup vs baseline: 2.0245x; 1.7161x over previous
#include <cuda_runtime.h>
#include <math.h>

#define H_IMG 1024
#define W_IMG 1280
#define NPIX  (H_IMG * W_IMG)
#define DAMPING 1e-6
#define DIST_THR_F 0.2f
#define NORM_THR_F 0.93969262078590838405f  /* cos(20 deg) */

#define NBLOCKS 288      // <= 2 CTAs/SM * 144 SMs: co-residency guaranteed on 148/152-SM parts
#define NTHREADS 256
#define NGROUPS (NPIX / 4)          // 327680 groups of 4 pixels
#define MAX_ITER 3

// Persistent state (no device allocation allowed).
__device__ double g_poseD[16];        // current pose, fp64, row-major 4x4
__device__ float  g_poseF[12];        // [0..8] R row-major, [9..11] t
__device__ double g_accum[28];        // 21 JtJ upper-tri, 6 JtR, 1 count
__device__ unsigned int g_arrive;     // barrier arrival counter
__device__ volatile unsigned int g_phase;  // completed-iteration counter

// ---------------------------------------------------------------------------
__global__ void icp_init(const float* __restrict__ pose10) {
    if (threadIdx.x == 0 && blockIdx.x == 0) {
        #pragma unroll
        for (int i = 0; i < 16; i++) g_poseD[i] = (double)pose10[i];
        #pragma unroll
        for (int r = 0; r < 3; r++) {
            #pragma unroll
            for (int c = 0; c < 3; c++) g_poseF[r * 3 + c] = pose10[r * 4 + c];
            g_poseF[9 + r] = pose10[r * 4 + 3];
        }
        #pragma unroll
        for (int i = 0; i < 28; i++) g_accum[i] = 0.0;
        g_arrive = 0;
        g_phase = 0;
    }
}

// ---------------------------------------------------------------------------
// fp64 solve on one thread: LDLT 6x6, se3 exp via Taylor-in-theta^2.
__device__ void solve_update(int write_out, float* out, int out_size)
{
    double A[6][6], b[6];
    {
        int k = 0;
        for (int i = 0; i < 6; i++)
            for (int j = i; j < 6; j++) { A[i][j] = g_accum[k]; A[j][i] = g_accum[k]; k++; }
        double tr = 0.0;
        for (int i = 0; i < 6; i++) tr += A[i][i];
        for (int i = 0; i < 6; i++) A[i][i] += tr * DAMPING;
        for (int i = 0; i < 6; i++) b[i] = g_accum[21 + i];
    }
    const double count = g_accum[27];

    // LDLT factorization (SPD by construction + damping)
    double L[6][6], D[6];
    for (int j = 0; j < 6; j++) {
        double dj = A[j][j];
        for (int k = 0; k < j; k++) dj -= L[j][k] * L[j][k] * D[k];
        D[j] = dj;
        L[j][j] = 1.0;
        for (int i = j + 1; i < 6; i++) {
            double v = A[i][j];
            for (int k = 0; k < j; k++) v -= L[i][k] * L[j][k] * D[k];
            L[i][j] = v / dj;
        }
    }
    double y[6];
    for (int i = 0; i < 6; i++) {
        double v = b[i];
        for (int k = 0; k < i; k++) v -= L[i][k] * y[k];
        y[i] = v;
    }
    double xi[6];
    for (int i = 5; i >= 0; i--) {
        double v = y[i] / D[i];
        for (int k = i + 1; k < 6; k++) v -= L[k][i] * xi[k];
        xi[i] = v;
    }
    for (int i = 0; i < 6; i++) xi[i] = -xi[i];

    // exp_se3(xi): even-series in theta^2 (exact to ~1e-15 for t2 < 0.25)
    const double w0 = xi[0], w1 = xi[1], w2 = xi[2];
    const double vx = xi[3], vy = xi[4], vz = xi[5];
    const double t2 = w0 * w0 + w1 * w1 + w2 * w2;
    double E[3][3], Jm[3][3];
    if (t2 <= 1e-16) {
        for (int i = 0; i < 3; i++)
            for (int j = 0; j < 3; j++) {
                E[i][j]  = (i == j) ? 1.0 : 0.0;
                Jm[i][j] = (i == j) ? 1.0 : 0.0;
            }
    } else {
        double cA, cB, cC;
        if (t2 < 0.25) {
            cA = 1.0 + t2 * (-1.0 / 6.0 + t2 * (1.0 / 120.0 + t2 * (-1.0 / 5040.0 +
                 t2 * (1.0 / 362880.0 + t2 * (-1.0 / 39916800.0)))));
            cB = 0.5 + t2 * (-1.0 / 24.0 + t2 * (1.0 / 720.0 + t2 * (-1.0 / 40320.0 +
                 t2 * (1.0 / 3628800.0 + t2 * (-1.0 / 479001600.0)))));
            cC = 1.0 / 6.0 + t2 * (-1.0 / 120.0 + t2 * (1.0 / 5040.0 + t2 * (-1.0 / 362880.0 +
                 t2 * (1.0 / 39916800.0 + t2 * (-1.0 / 6227020800.0)))));
        } else {
            const double th = sqrt(t2);
            const double st = sin(th), ct = cos(th);
            cA = st / th;
            cB = (1.0 - ct) / t2;
            cC = (th - st) / (t2 * th);
        }
        const double wh[3][3] = { {0.0, -w2,  w1}, { w2, 0.0, -w0}, {-w1,  w0, 0.0} };
        double wh2[3][3];
        for (int i = 0; i < 3; i++)
            for (int j = 0; j < 3; j++) {
                double acc = 0.0;
                for (int k = 0; k < 3; k++) acc += wh[i][k] * wh[k][j];
                wh2[i][j] = acc;
            }
        for (int i = 0; i < 3; i++)
            for (int j = 0; j < 3; j++) {
                const double eye = (i == j) ? 1.0 : 0.0;
                E[i][j]  = eye + cA * wh[i][j] + cB * wh2[i][j];
                Jm[i][j] = eye + cB * wh[i][j] + cC * wh2[i][j];
            }
    }
    double T[16];
    for (int i = 0; i < 3; i++) {
        for (int j = 0; j < 3; j++) T[i * 4 + j] = E[i][j];
        T[i * 4 + 3] = Jm[i][0] * vx + Jm[i][1] * vy + Jm[i][2] * vz;
    }
    T[12] = 0.0; T[13] = 0.0; T[14] = 0.0; T[15] = 1.0;

    double P[16];
    for (int i = 0; i < 4; i++)
        for (int j = 0; j < 4; j++) {
            double acc = 0.0;
            for (int k = 0; k < 4; k++) acc += T[i * 4 + k] * g_poseD[k * 4 + j];
            P[i * 4 + j] = acc;
        }
    for (int i = 0; i < 16; i++) g_poseD[i] = P[i];
    for (int r = 0; r < 3; r++) {
        for (int c = 0; c < 3; c++) g_poseF[r * 3 + c] = (float)P[r * 4 + c];
        g_poseF[9 + r] = (float)P[r * 4 + 3];
    }

    if (write_out) {
        for (int i = 0; i < 16 && i < out_size; i++) out[i] = (float)P[i];
        if (out_size >= 17) out[16] = (float)(count / (double)NPIX);
    }
    for (int i = 0; i < 28; i++) g_accum[i] = 0.0;
}

// ---------------------------------------------------------------------------
// Per-pixel body: branchless accumulate; exact-rounding intrinsics keep the
// round(u/v) discretization identical under --use_fast_math.
__device__ __forceinline__ void px_body(
    float x, float y, float z, float nx, float ny, float nz,
    const float* __restrict__ v1d, const float* __restrict__ n1d,
    float fx, float fy, float cx, float cy,
    float R00, float R01, float R02, float R10, float R11, float R12,
    float R20, float R21, float R22, float tx, float ty, float tz,
    float* s)
{
    const float px = __fmaf_rn(x, R00, __fmaf_rn(y, R01, __fmaf_rn(z, R02, tx)));
    const float py = __fmaf_rn(x, R10, __fmaf_rn(y, R11, __fmaf_rn(z, R12, ty)));
    const float pz = __fmaf_rn(x, R20, __fmaf_rn(y, R21, __fmaf_rn(z, R22, tz)));

    const float qx = __fmaf_rn(nx, R00, __fmaf_rn(ny, R01, __fmul_rn(nz, R02)));
    const float qy = __fmaf_rn(nx, R10, __fmaf_rn(ny, R11, __fmul_rn(nz, R12)));
    const float qz = __fmaf_rn(nx, R20, __fmaf_rn(ny, R21, __fmul_rn(nz, R22)));

    const float u = __fadd_rn(__fmul_rn(__fdiv_rn(px, pz), fx), cx);
    const float v = __fadd_rn(__fmul_rn(__fdiv_rn(py, pz), fy), cy);
    const bool inview = (u > 0.f) && (u < (float)(W_IMG - 1)) &&
                        (v > 0.f) && (v < (float)(H_IMG - 1));

    const float uif = fminf(fmaxf(rintf(u), 0.f), (float)(W_IMG - 1));
    const float vif = fminf(fmaxf(rintf(v), 0.f), (float)(H_IMG - 1));
    const int g = (int)vif * W_IMG + (int)uif;

    const float ax = v1d[3 * g + 0];
    const float ay = v1d[3 * g + 1];
    const float az = v1d[3 * g + 2];
    const float bx = n1d[3 * g + 0];
    const float by = n1d[3 * g + 1];
    const float bz = n1d[3 * g + 2];

    const float dx = __fadd_rn(px, -ax);
    const float dy = __fadd_rn(py, -ay);
    const float dz = __fadd_rn(pz, -az);
    const float dist = __fsqrt_rn(__fmaf_rn(dx, dx, __fmaf_rn(dy, dy, __fmul_rn(dz, dz))));
    const float ndot = __fmaf_rn(qx, bx, __fmaf_rn(qy, by, __fmul_rn(qz, bz)));

    const bool valid = inview && !(dist > DIST_THR_F) &&
                       (z > 0.f) && (az > 0.f) && (ndot > NORM_THR_F);

    float r = __fmaf_rn(bx, dx, __fmaf_rn(by, dy, __fmul_rn(bz, dz)));
    float J[6];
    J[0] = __fadd_rn(__fmul_rn(py, bz), -__fmul_rn(pz, by));
    J[1] = __fadd_rn(__fmul_rn(pz, bx), -__fmul_rn(px, bz));
    J[2] = __fadd_rn(__fmul_rn(px, by), -__fmul_rn(py, bx));
    J[3] = bx; J[4] = by; J[5] = bz;
    if (!valid) {
        r = 0.f;
        #pragma unroll
        for (int i = 0; i < 6; i++) J[i] = 0.f;
    }
    int k = 0;
    #pragma unroll
    for (int i = 0; i < 6; i++)
        #pragma unroll
        for (int j = i; j < 6; j++) { s[k] = __fmaf_rn(J[i], J[j], s[k]); k++; }
    #pragma unroll
    for (int i = 0; i < 6; i++) s[21 + i] = __fmaf_rn(J[i], r, s[21 + i]);
    if (valid) s[27] += 1.f;
}

// ---------------------------------------------------------------------------
// Persistent kernel: all 3 ICP iterations in one launch with a software grid
// barrier. __launch_bounds__(256,2) caps regs at 128 -> 2 CTAs/SM guaranteed,
// and NBLOCKS=288 <= 2*144 so every CTA is resident in wave 1 (no deadlock).
__global__ __launch_bounds__(NTHREADS, 2)
void icp_persistent(const float* __restrict__ v0d, const float* __restrict__ v1d,
                    const float* __restrict__ n0d, const float* __restrict__ n1d,
                    const float* __restrict__ Km,
                    float* __restrict__ out, int out_size)
{
    const float fx = Km[0], cx = Km[2], fy = Km[4], cy = Km[5];
    const int tglob = blockIdx.x * NTHREADS + threadIdx.x;
    const int ntot  = NBLOCKS * NTHREADS;

    __shared__ double sh[28];
    __shared__ unsigned int s_last;

    for (int it = 0; it < MAX_ITER; ++it) {
        // pose broadcast (updated by solver before phase release)
        const float R00 = g_poseF[0], R01 = g_poseF[1], R02 = g_poseF[2];
        const float R10 = g_poseF[3], R11 = g_poseF[4], R12 = g_poseF[5];
        const float R20 = g_poseF[6], R21 = g_poseF[7], R22 = g_poseF[8];
        const float tx  = g_poseF[9], ty  = g_poseF[10], tz = g_poseF[11];

        float s[28];
        #pragma unroll
        for (int i = 0; i < 28; i++) s[i] = 0.f;

        // grid-stride over groups of 4 consecutive pixels (3 float4 per array)
        for (int t = tglob; t < NGROUPS; t += ntot) {
            const float4* v0q = (const float4*)(v0d) + 3 * t;
            const float4* n0q = (const float4*)(n0d) + 3 * t;
            const float4 a0 = v0q[0], a1 = v0q[1], a2 = v0q[2];
            const float4 b0 = n0q[0], b1 = n0q[1], b2 = n0q[2];
            px_body(a0.x, a0.y, a0.z, b0.x, b0.y, b0.z, v1d, n1d, fx, fy, cx, cy,
                    R00, R01, R02, R10, R11, R12, R20, R21, R22, tx, ty, tz, s);
            px_body(a0.w, a1.x, a1.y, b0.w, b1.x, b1.y, v1d, n1d, fx, fy, cx, cy,
                    R00, R01, R02, R10, R11, R12, R20, R21, R22, tx, ty, tz, s);
            px_body(a1.z, a1.w, a2.x, b1.z, b1.w, b2.x, v1d, n1d, fx, fy, cx, cy,
                    R00, R01, R02, R10, R11, R12, R20, R21, R22, tx, ty, tz, s);
            px_body(a2.y, a2.z, a2.w, b2.y, b2.z, b2.w, v1d, n1d, fx, fy, cx, cy,
                    R00, R01, R02, R10, R11, R12, R20, R21, R22, tx, ty, tz, s);
        }

        // warp reduction
        #pragma unroll
        for (int i = 0; i < 28; i++) {
            #pragma unroll
            for (int o = 16; o > 0; o >>= 1)
                s[i] += __shfl_down_sync(0xffffffffu, s[i], o);
        }

        if (threadIdx.x < 28) sh[threadIdx.x] = 0.0;
        __syncthreads();
        if ((threadIdx.x & 31) == 0) {
            #pragma unroll
            for (int i = 0; i < 28; i++) atomicAdd(&sh[i], (double)s[i]);
        }
        __syncthreads();
        if (threadIdx.x < 28) atomicAdd(&g_accum[threadIdx.x], sh[threadIdx.x]);

        // ---- grid barrier + inline solve by the last-arriving CTA ----
        if (threadIdx.x == 0) {
            __threadfence();
            s_last = atomicAdd(&g_arrive, 1u);
        }
        __syncthreads();
        const bool is_solver = (s_last == (unsigned)(gridDim.x * (it + 1) - 1));
        if (is_solver && threadIdx.x == 0) {
            solve_update(it == MAX_ITER - 1 ? 1 : 0, out, out_size);
            __threadfence();
            g_phase = it + 1;   // release
        }
        if (it < MAX_ITER - 1) {
            if (threadIdx.x == 0) {
                while (g_phase < (unsigned)(it + 1)) { __nanosleep(200); }
            }
            __syncthreads();
            __threadfence();
        }
    }
}

// ---------------------------------------------------------------------------
extern "C" void kernel_launch(void* const* d_in, const int* in_sizes, int n_in,
                              void* d_out, int out_size)
{
    const float* pose10 = (const float*)d_in[0];  // 16
    const float* v0     = (const float*)d_in[1];  // H*W*3
    const float* v1     = (const float*)d_in[2];  // H*W*3
    const float* n0     = (const float*)d_in[3];  // H*W*3
    const float* n1     = (const float*)d_in[4];  // H*W*3
    const float* K      = (const float*)d_in[5];  // 9
    float* out = (float*)d_out;

    icp_init<<<1, 32>>>(pose10);
    icp_persistent<<<NBLOCKS, NTHREADS>>>(v0, v1, n0, n1, K, out, out_size);
}